// round 1
// baseline (speedup 1.0000x reference)
#include <cuda_runtime.h>
#include <math.h>

#define Bc   4
#define Sc   2048
#define HIDc 1024
#define Hc   16
#define Dc   64
#define MROWS (Bc*Sc)        // 8192
#define BHc  (Bc*Hc)         // 64

// Scratch for projected Q, K, V in [B, H, S, D] layout (allocation-free).
__device__ float g_Q[(size_t)BHc * Sc * Dc];
__device__ float g_K[(size_t)BHc * Sc * Dc];
__device__ float g_V[(size_t)BHc * Sc * Dc];

// ---------------------------------------------------------------------------
// Projection GEMM: C[m,n] = sum_k X[m,k] * W[n,k] + bias[n]
// X: [8192, 1024] row-major, W: [1024, 1024] row-major (torch Linear weight)
// Output written permuted into [B, H, S, D]:  m=(b,s), n=(h,d)
// Tiles: BM=64, BN=64, BK=16; 256 threads; 4x4 microtile per thread.
// ---------------------------------------------------------------------------
__global__ __launch_bounds__(256) void proj_kernel(
    const float* __restrict__ X, const float* __restrict__ W,
    const float* __restrict__ bias, float* __restrict__ out)
{
    __shared__ float As[16][64];
    __shared__ float Bs[16][64];

    const int tid = threadIdx.x;
    const int tx  = tid & 15;
    const int ty  = tid >> 4;
    const int m0  = blockIdx.y * 64;
    const int n0  = blockIdx.x * 64;
    const int lr  = tid >> 2;        // 0..63 (tile row for loads)
    const int lc  = (tid & 3) * 4;   // 0,4,8,12 (k offset for loads)

    float c[4][4] = {};

    for (int k0 = 0; k0 < 1024; k0 += 16) {
        float4 av = *(const float4*)&X[(size_t)(m0 + lr) * 1024 + k0 + lc];
        float4 bv = *(const float4*)&W[(size_t)(n0 + lr) * 1024 + k0 + lc];
        As[lc + 0][lr] = av.x; As[lc + 1][lr] = av.y;
        As[lc + 2][lr] = av.z; As[lc + 3][lr] = av.w;
        Bs[lc + 0][lr] = bv.x; Bs[lc + 1][lr] = bv.y;
        Bs[lc + 2][lr] = bv.z; Bs[lc + 3][lr] = bv.w;
        __syncthreads();

        #pragma unroll
        for (int kk = 0; kk < 16; kk++) {
            float4 a = *(const float4*)&As[kk][ty * 4];
            float4 b = *(const float4*)&Bs[kk][tx * 4];
            c[0][0] += a.x * b.x; c[0][1] += a.x * b.y; c[0][2] += a.x * b.z; c[0][3] += a.x * b.w;
            c[1][0] += a.y * b.x; c[1][1] += a.y * b.y; c[1][2] += a.y * b.z; c[1][3] += a.y * b.w;
            c[2][0] += a.z * b.x; c[2][1] += a.z * b.y; c[2][2] += a.z * b.z; c[2][3] += a.z * b.w;
            c[3][0] += a.w * b.x; c[3][1] += a.w * b.y; c[3][2] += a.w * b.z; c[3][3] += a.w * b.w;
        }
        __syncthreads();
    }

    // n0 is a multiple of 64 => head h is constant for the whole block
    const int h = n0 >> 6;
    #pragma unroll
    for (int i = 0; i < 4; i++) {
        const int m  = m0 + ty * 4 + i;
        const int b_ = m >> 11;           // m / 2048
        const int s  = m & 2047;
        const int d  = tx * 4;            // within-head dim, contiguous x4
        float4 o;
        o.x = c[i][0] + bias[n0 + d + 0];
        o.y = c[i][1] + bias[n0 + d + 1];
        o.z = c[i][2] + bias[n0 + d + 2];
        o.w = c[i][3] + bias[n0 + d + 3];
        *(float4*)&out[(((size_t)b_ * 16 + h) * 2048 + s) * 64 + d] = o;
    }
}

// ---------------------------------------------------------------------------
// Scores: per (b,h): P[q,k] = scale * Q[q,:]·K[k,:], masked_fill(mask==0, -1e9)
// NT GEMM, M=N=2048, K=64. Raw masked scores written to attn output region.
// ---------------------------------------------------------------------------
__global__ __launch_bounds__(256) void scores_kernel(
    const float* __restrict__ Q, const float* __restrict__ K,
    const int* __restrict__ mask, float* __restrict__ attn)
{
    const int bh = blockIdx.z;
    const float* Qh = Q + (size_t)bh * Sc * Dc;
    const float* Kh = K + (size_t)bh * Sc * Dc;
    float* Ph = attn + (size_t)bh * Sc * Sc;

    __shared__ float As[16][64];
    __shared__ float Bs[16][64];

    const int tid = threadIdx.x;
    const int tx  = tid & 15;
    const int ty  = tid >> 4;
    const int m0  = blockIdx.y * 64;
    const int n0  = blockIdx.x * 64;
    const int lr  = tid >> 2;
    const int lc  = (tid & 3) * 4;

    float c[4][4] = {};

    #pragma unroll
    for (int k0 = 0; k0 < 64; k0 += 16) {
        float4 av = *(const float4*)&Qh[(size_t)(m0 + lr) * 64 + k0 + lc];
        float4 bv = *(const float4*)&Kh[(size_t)(n0 + lr) * 64 + k0 + lc];
        As[lc + 0][lr] = av.x; As[lc + 1][lr] = av.y;
        As[lc + 2][lr] = av.z; As[lc + 3][lr] = av.w;
        Bs[lc + 0][lr] = bv.x; Bs[lc + 1][lr] = bv.y;
        Bs[lc + 2][lr] = bv.z; Bs[lc + 3][lr] = bv.w;
        __syncthreads();

        #pragma unroll
        for (int kk = 0; kk < 16; kk++) {
            float4 a = *(const float4*)&As[kk][ty * 4];
            float4 b = *(const float4*)&Bs[kk][tx * 4];
            c[0][0] += a.x * b.x; c[0][1] += a.x * b.y; c[0][2] += a.x * b.z; c[0][3] += a.x * b.w;
            c[1][0] += a.y * b.x; c[1][1] += a.y * b.y; c[1][2] += a.y * b.z; c[1][3] += a.y * b.w;
            c[2][0] += a.z * b.x; c[2][1] += a.z * b.y; c[2][2] += a.z * b.z; c[2][3] += a.z * b.w;
            c[3][0] += a.w * b.x; c[3][1] += a.w * b.y; c[3][2] += a.w * b.z; c[3][3] += a.w * b.w;
        }
        __syncthreads();
    }

    const int b_ = bh >> 4;
    const int* mb = mask + (size_t)b_ * Sc * Sc;
    const float scale = 0.125f;   // 1/sqrt(64)

    #pragma unroll
    for (int i = 0; i < 4; i++) {
        const int q = m0 + ty * 4 + i;
        const int k = n0 + tx * 4;
        const int4 mm = *(const int4*)&mb[(size_t)q * Sc + k];
        float4 o;
        o.x = (mm.x == 0) ? -1e9f : c[i][0] * scale;
        o.y = (mm.y == 0) ? -1e9f : c[i][1] * scale;
        o.z = (mm.z == 0) ? -1e9f : c[i][2] * scale;
        o.w = (mm.w == 0) ? -1e9f : c[i][3] * scale;
        *(float4*)&Ph[(size_t)q * Sc + k] = o;
    }
}

// ---------------------------------------------------------------------------
// Row softmax in place. One block per row of 2048 floats; values held in regs.
// ---------------------------------------------------------------------------
__global__ __launch_bounds__(256) void softmax_kernel(float* __restrict__ attn)
{
    float* p = attn + (size_t)blockIdx.x * Sc;
    const int tid = threadIdx.x;

    float v[8];
    float mx = -3.4e38f;
    #pragma unroll
    for (int i = 0; i < 8; i++) {
        v[i] = p[tid + i * 256];
        mx = fmaxf(mx, v[i]);
    }

    __shared__ float red_m[8];
    __shared__ float red_s[8];

    #pragma unroll
    for (int o = 16; o > 0; o >>= 1) mx = fmaxf(mx, __shfl_xor_sync(0xFFFFFFFFu, mx, o));
    if ((tid & 31) == 0) red_m[tid >> 5] = mx;
    __syncthreads();
    mx = red_m[0];
    #pragma unroll
    for (int i = 1; i < 8; i++) mx = fmaxf(mx, red_m[i]);

    float sum = 0.0f;
    #pragma unroll
    for (int i = 0; i < 8; i++) {
        v[i] = expf(v[i] - mx);
        sum += v[i];
    }
    #pragma unroll
    for (int o = 16; o > 0; o >>= 1) sum += __shfl_xor_sync(0xFFFFFFFFu, sum, o);
    if ((tid & 31) == 0) red_s[tid >> 5] = sum;
    __syncthreads();
    sum = 0.0f;
    #pragma unroll
    for (int i = 0; i < 8; i++) sum += red_s[i];

    const float inv = 1.0f / sum;
    #pragma unroll
    for (int i = 0; i < 8; i++) p[tid + i * 256] = v[i] * inv;
}

// ---------------------------------------------------------------------------
// PV: per (b,h): ctx[q,d] = sum_k P[q,k] * V[k,d].  NN GEMM, M=2048,N=64,K=2048.
// ctx written in [B, S, H*D] layout.
// ---------------------------------------------------------------------------
__global__ __launch_bounds__(256) void pv_kernel(
    const float* __restrict__ attn, const float* __restrict__ V,
    float* __restrict__ ctx)
{
    const int bh = blockIdx.z;
    const float* Ph = attn + (size_t)bh * Sc * Sc;
    const float* Vh = V + (size_t)bh * Sc * Dc;

    __shared__ float As[16][64];
    __shared__ float Bs[16][64];

    const int tid = threadIdx.x;
    const int tx  = tid & 15;
    const int ty  = tid >> 4;
    const int m0  = blockIdx.y * 64;
    const int lr  = tid >> 2;
    const int lc  = (tid & 3) * 4;
    const int br  = tid >> 4;        // 0..15
    const int bc  = (tid & 15) * 4;  // 0..60

    float c[4][4] = {};

    for (int k0 = 0; k0 < 2048; k0 += 16) {
        float4 av = *(const float4*)&Ph[(size_t)(m0 + lr) * Sc + k0 + lc];
        As[lc + 0][lr] = av.x; As[lc + 1][lr] = av.y;
        As[lc + 2][lr] = av.z; As[lc + 3][lr] = av.w;
        *(float4*)&Bs[br][bc] = *(const float4*)&Vh[(size_t)(k0 + br) * 64 + bc];
        __syncthreads();

        #pragma unroll
        for (int kk = 0; kk < 16; kk++) {
            float4 a = *(const float4*)&As[kk][ty * 4];
            float4 b = *(const float4*)&Bs[kk][tx * 4];
            c[0][0] += a.x * b.x; c[0][1] += a.x * b.y; c[0][2] += a.x * b.z; c[0][3] += a.x * b.w;
            c[1][0] += a.y * b.x; c[1][1] += a.y * b.y; c[1][2] += a.y * b.z; c[1][3] += a.y * b.w;
            c[2][0] += a.z * b.x; c[2][1] += a.z * b.y; c[2][2] += a.z * b.z; c[2][3] += a.z * b.w;
            c[3][0] += a.w * b.x; c[3][1] += a.w * b.y; c[3][2] += a.w * b.z; c[3][3] += a.w * b.w;
        }
        __syncthreads();
    }

    const int b_ = bh >> 4;
    const int h  = bh & 15;
    #pragma unroll
    for (int i = 0; i < 4; i++) {
        const int q = m0 + ty * 4 + i;
        const int d = tx * 4;
        float4 o = make_float4(c[i][0], c[i][1], c[i][2], c[i][3]);
        *(float4*)&ctx[((size_t)b_ * 2048 + q) * 1024 + h * 64 + d] = o;
    }
}

// ---------------------------------------------------------------------------
extern "C" void kernel_launch(void* const* d_in, const int* in_sizes, int n_in,
                              void* d_out, int out_size)
{
    (void)in_sizes; (void)n_in; (void)out_size;

    const float* query  = (const float*)d_in[0];
    const float* key_in = (const float*)d_in[1];
    const float* value  = (const float*)d_in[2];
    const int*   mask   = (const int*)  d_in[3];
    const float* w_q    = (const float*)d_in[4];
    const float* b_q    = (const float*)d_in[5];
    const float* w_k    = (const float*)d_in[6];
    const float* b_k    = (const float*)d_in[7];
    const float* w_v    = (const float*)d_in[8];
    const float* b_v    = (const float*)d_in[9];

    float* ctx  = (float*)d_out;
    float* attn = (float*)d_out + (size_t)Bc * Sc * HIDc;  // ctx first, then attn

    float *Q, *K, *V;
    cudaGetSymbolAddress((void**)&Q, g_Q);
    cudaGetSymbolAddress((void**)&K, g_K);
    cudaGetSymbolAddress((void**)&V, g_V);

    dim3 gp(HIDc / 64, MROWS / 64);          // (16, 128)
    proj_kernel<<<gp, 256>>>(query,  w_q, b_q, Q);
    proj_kernel<<<gp, 256>>>(key_in, w_k, b_k, K);
    proj_kernel<<<gp, 256>>>(value,  w_v, b_v, V);

    dim3 gs(Sc / 64, Sc / 64, BHc);          // (32, 32, 64)
    scores_kernel<<<gs, 256>>>(Q, K, mask, attn);

    softmax_kernel<<<(unsigned)((size_t)BHc * Sc), 256>>>(attn);

    dim3 gv(1, Sc / 64, BHc);                // (1, 32, 64)
    pv_kernel<<<gv, 256>>>(attn, V, ctx);
}